// round 14
// baseline (speedup 1.0000x reference)
#include <cuda_runtime.h>
#include <cuda_fp16.h>
#include <cstdint>

// ---------------- problem dims ----------------
#define MTOT 8192
#define NTOT 11008
#define KTOT 4096

// ---------------- GEMM tiling ----------------
#define BM 128
#define BN 128
#define BK 64
#define NITER (KTOT / BK)                  // 64
#define A_BYTES (BM * BK * 2)              // 16384
#define B_BYTES (BN * BK * 2)              // 16384
#define STG_BYTES (A_BYTES + B_BYTES)      // 32768
#define STAGES 3
#define SMEM_TOTAL (STAGES * STG_BYTES)    // 98304 per CTA -> 2 CTAs/SM
#define NBLK (NTOT / BN)                   // 86
#define MBLK (MTOT / BM)                   // 64
#define GROUP_M 8

// ---------------- device-global scratch (allowed) ----------------
__device__ __align__(1024) __half g_A[(size_t)MTOT * KTOT];   // exact int8 q as fp16
__device__ __align__(1024) __half g_B[(size_t)NTOT * KTOT];   // dequantized weights fp16
__device__ float g_as[MTOT];                                   // per-token activation scale
__device__ int g_w_is_i32;                                     // weight buffer layout flag

// ---------------- ptx helpers ----------------
static __device__ __forceinline__ uint32_t smem_u32(const void* p) {
    uint32_t a;
    asm("{ .reg .u64 t; cvta.to.shared.u64 t, %1; cvt.u32.u64 %0, t; }" : "=r"(a) : "l"(p));
    return a;
}

#define CP16(dst, src) \
    asm volatile("cp.async.cg.shared.global [%0], [%1], 16;" :: "r"(dst), "l"(src) : "memory")
#define CP_COMMIT() asm volatile("cp.async.commit_group;" ::: "memory")
#define CP_WAIT(n)  asm volatile("cp.async.wait_group %0;" :: "n"(n) : "memory")

static __device__ __forceinline__ void ldsm_x4(uint32_t* r, uint32_t addr) {
    asm volatile("ldmatrix.sync.aligned.m8n8.x4.shared.b16 {%0,%1,%2,%3}, [%4];"
                 : "=r"(r[0]), "=r"(r[1]), "=r"(r[2]), "=r"(r[3]) : "r"(addr));
}

static __device__ __forceinline__ void mma16816(float* d, const uint32_t* a,
                                                uint32_t b0, uint32_t b1) {
    asm volatile("mma.sync.aligned.m16n8k16.row.col.f32.f16.f16.f32 "
                 "{%0,%1,%2,%3}, {%4,%5,%6,%7}, {%8,%9}, {%0,%1,%2,%3};"
                 : "+f"(d[0]), "+f"(d[1]), "+f"(d[2]), "+f"(d[3])
                 : "r"(a[0]), "r"(a[1]), "r"(a[2]), "r"(a[3]), "r"(b0), "r"(b1));
}

// ==================== kernel 0: detect weight element width (parallel) =============
__global__ void detect_kernel(const int* __restrict__ w) {
    __shared__ int flag;
    int t = threadIdx.x;
    if (t == 0) flag = 1;
    __syncthreads();
    unsigned v = (unsigned)w[t];
    if (v >= 16u) flag = 0;        // benign race: all writers store 0
    __syncthreads();
    if (t == 0) g_w_is_i32 = flag;
}

// ==================== kernel 1: per-token int8 fake-quant -> fp16 ====================
__global__ void __launch_bounds__(256) quant_kernel(const float* __restrict__ x) {
    int row = blockIdx.x;
    int t = threadIdx.x;
    const float4* xr = (const float4*)(x + (size_t)row * KTOT);

    float4 v[4];
    float amax = 0.0f;
#pragma unroll
    for (int j = 0; j < 4; j++) {
        v[j] = xr[t + j * 256];
        amax = fmaxf(amax, fmaxf(fmaxf(fabsf(v[j].x), fabsf(v[j].y)),
                                 fmaxf(fabsf(v[j].z), fabsf(v[j].w))));
    }
#pragma unroll
    for (int o = 16; o; o >>= 1) amax = fmaxf(amax, __shfl_xor_sync(0xFFFFFFFFu, amax, o));
    __shared__ float red[8];
    if ((t & 31) == 0) red[t >> 5] = amax;
    __syncthreads();
    if (t < 32) {
        float m = (t < 8) ? red[t] : 0.0f;
#pragma unroll
        for (int o = 4; o; o >>= 1) m = fmaxf(m, __shfl_xor_sync(0xFFFFFFFFu, m, o));
        if (t == 0) red[0] = m;
    }
    __syncthreads();
    amax = red[0];
    float s = fmaxf(amax, 1e-12f) / 127.0f;
    if (t == 0) g_as[row] = s;

    __half* dst = g_A + (size_t)row * KTOT;
#pragma unroll
    for (int j = 0; j < 4; j++) {
        int f = t + j * 256;
        float q0 = fminf(fmaxf(rintf(v[j].x / s), -128.0f), 127.0f);
        float q1 = fminf(fmaxf(rintf(v[j].y / s), -128.0f), 127.0f);
        float q2 = fminf(fmaxf(rintf(v[j].z / s), -128.0f), 127.0f);
        float q3 = fminf(fmaxf(rintf(v[j].w / s), -128.0f), 127.0f);
        __half2 h01 = __floats2half2_rn(q0, q1);
        __half2 h23 = __floats2half2_rn(q2, q3);
        uint2 st;
        st.x = *(uint32_t*)&h01;
        st.y = *(uint32_t*)&h23;
        ((uint2*)dst)[f] = st;
    }
}

// ==================== kernel 2: int4 groupwise dequant -> fp16 (dual-format) ====
__global__ void __launch_bounds__(256) dequant_kernel(const void* __restrict__ wraw,
                                                      const float* __restrict__ sc,
                                                      const float* __restrict__ zr) {
    int row = blockIdx.x;
    int t = threadIdx.x;                       // 16 elements per thread
    float scale = sc[row * 128 + (t >> 1)];
    float zero  = zr[row * 128 + (t >> 1)];

    float f[16];
    if (g_w_is_i32) {
        const int4* p = (const int4*)((const int*)wraw + (size_t)row * KTOT + t * 16);
#pragma unroll
        for (int j = 0; j < 4; j++) {
            int4 v = p[j];
            f[j * 4 + 0] = (float)v.x;
            f[j * 4 + 1] = (float)v.y;
            f[j * 4 + 2] = (float)v.z;
            f[j * 4 + 3] = (float)v.w;
        }
    } else {
        int4 q = ((const int4*)((const int8_t*)wraw + (size_t)row * KTOT))[t];
        const int* qi = (const int*)&q;
#pragma unroll
        for (int i = 0; i < 4; i++) {
            int word = qi[i];
#pragma unroll
            for (int b = 0; b < 4; b++)
                f[i * 4 + b] = (float)((word >> (8 * b)) & 0xFF);
        }
    }

    __half h[16];
#pragma unroll
    for (int i = 0; i < 16; i++) h[i] = __float2half_rn((f[i] - zero) * scale);

    const uint32_t* hw = (const uint32_t*)h;
    uint4 s0, s1;
    s0.x = hw[0]; s0.y = hw[1]; s0.z = hw[2]; s0.w = hw[3];
    s1.x = hw[4]; s1.y = hw[5]; s1.z = hw[6]; s1.w = hw[7];
    uint4* dst = (uint4*)(g_B + (size_t)row * KTOT + t * 16);
    dst[0] = s0;
    dst[1] = s1;
}

// ==================== kernel 3: HMMA GEMM (64x64 warp tile, grouped raster) ========
// SMEM per stage: A [128 rows x 128B], B [128 rows x 128B].
// 16B chunk (r, c16) stored at byte r*128 + ((c16 ^ (r&7)) * 16).

static __device__ __forceinline__ void fetch_stage(uint32_t sb, int s, int ki,
                                                   int m0, int n0, int t) {
    uint32_t abase = sb + s * STG_BYTES;
    uint32_t bbase = abase + A_BYTES;
    size_t k0 = (size_t)ki * BK;
    int r0 = t >> 3, c = t & 7;
    uint32_t sw = (uint32_t)c;
    const char* gA = (const char*)(g_A + (size_t)m0 * KTOT + k0) + c * 16;
    const char* gB = (const char*)(g_B + (size_t)n0 * KTOT + k0) + c * 16;
#pragma unroll
    for (int j = 0; j < 8; j++) {
        int r = r0 + j * 16;
        uint32_t off = (uint32_t)(r * 128) + ((sw ^ (r & 7)) * 16);
        CP16(abase + off, gA + (size_t)r * (KTOT * 2));
    }
#pragma unroll
    for (int j = 0; j < 8; j++) {
        int r = r0 + j * 16;
        uint32_t off = (uint32_t)(r * 128) + ((sw ^ (r & 7)) * 16);
        CP16(bbase + off, gB + (size_t)r * (KTOT * 2));
    }
    CP_COMMIT();
}

__global__ void __launch_bounds__(128, 2) gemm_kernel(float* __restrict__ out) {
    extern __shared__ char smem[];
    uint32_t sb = smem_u32(smem);
    int t = threadIdx.x, wid = t >> 5, l = t & 31;

    // grouped rasterization: 8 m-blocks x 86 n-blocks per group -> wave working
    // set ~45MB (A 8MB + B 37MB), fits L2.
    int pid = blockIdx.x;
    const int group_size = GROUP_M * NBLK;          // 688
    int group_id = pid / group_size;
    int rem = pid - group_id * group_size;
    int m_blk = group_id * GROUP_M + (rem % GROUP_M);
    int n_blk = rem / GROUP_M;
    int m0 = m_blk * BM;
    int n0 = n_blk * BN;

    int wm = (wid & 1) * 64;          // 2 warps along M (64 each)
    int wn = (wid >> 1) * 64;         // 2 warps along N (64 each)

    float acc[4][8][4];
#pragma unroll
    for (int i = 0; i < 4; i++)
#pragma unroll
        for (int j = 0; j < 8; j++)
#pragma unroll
            for (int q = 0; q < 4; q++) acc[i][j][q] = 0.0f;

    // ldmatrix lane->row/chunk components
    int a_r = wm + (l & 15);                    // + mt*16
    int b_r = wn + (l & 7) + ((l >> 4) << 3);   // + np*16
    int a_chi = l >> 4;                         // A chunk: ks*2 + (l>>4)
    int b_chi = (l >> 3) & 1;                   // B chunk: ks*2 + ((l>>3)&1)

    // prologue: stages 0,1
    fetch_stage(sb, 0, 0, m0, n0, t);
    fetch_stage(sb, 1, 1, m0, n0, t);

    for (int i = 0; i < NITER; i++) {
        CP_WAIT(1);                 // fetch(i) complete (newest outstanding = fetch(i+1))
        __syncthreads();            // visibility + WAR guard for the fetch below

        // fetch stage i+2 BEFORE compute: overwrites stage (i-1)%3 whose readers
        // all passed sync(i) -> safe; gives cp.async a full iter of lead and
        // overlaps LSU with the mma stream.
        fetch_stage(sb, (i + 2) % 3, (i + 2) & (NITER - 1), m0, n0, t);

        uint32_t abase = sb + (i % 3) * STG_BYTES;
        uint32_t bbase = abase + A_BYTES;

#pragma unroll
        for (int ks = 0; ks < 4; ks++) {
            uint32_t af[4][4], bf[4][4];
#pragma unroll
            for (int mt = 0; mt < 4; mt++) {
                int r = a_r + mt * 16;
                uint32_t c16 = (uint32_t)(ks * 2 + a_chi);
                uint32_t addr = abase + (uint32_t)(r * 128) + ((c16 ^ (r & 7)) * 16);
                ldsm_x4(af[mt], addr);
            }
#pragma unroll
            for (int np = 0; np < 4; np++) {
                int r = b_r + np * 16;
                uint32_t c16 = (uint32_t)(ks * 2 + b_chi);
                uint32_t addr = bbase + (uint32_t)(r * 128) + ((c16 ^ (r & 7)) * 16);
                ldsm_x4(bf[np], addr);
            }
#pragma unroll
            for (int mt = 0; mt < 4; mt++)
#pragma unroll
                for (int np = 0; np < 4; np++) {
                    mma16816(acc[mt][np * 2],     af[mt], bf[np][0], bf[np][1]);
                    mma16816(acc[mt][np * 2 + 1], af[mt], bf[np][2], bf[np][3]);
                }
        }
    }

    // epilogue: per-row activation scale, direct float2 stores
    int gid = l >> 2;
    int cl = (l & 3) * 2;
#pragma unroll
    for (int mt = 0; mt < 4; mt++) {
        int row0 = m0 + wm + mt * 16 + gid;
        float s0 = g_as[row0];
        float s1 = g_as[row0 + 8];
        float* o0 = out + (size_t)row0 * NTOT + n0 + wn + cl;
        float* o1 = o0 + (size_t)8 * NTOT;
#pragma unroll
        for (int nt = 0; nt < 8; nt++) {
            float2 v0 = make_float2(acc[mt][nt][0] * s0, acc[mt][nt][1] * s0);
            float2 v1 = make_float2(acc[mt][nt][2] * s1, acc[mt][nt][3] * s1);
            *(float2*)(o0 + nt * 8) = v0;
            *(float2*)(o1 + nt * 8) = v1;
        }
    }
}

// ==================== launch ====================
extern "C" void kernel_launch(void* const* d_in, const int* in_sizes, int n_in,
                              void* d_out, int out_size) {
    const float* x  = nullptr;
    const void*  w  = nullptr;
    const float* sc = nullptr;
    const float* zr = nullptr;
    for (int i = 0; i < n_in; i++) {
        long long sz = (long long)in_sizes[i];
        if (sz == (long long)MTOT * KTOT)        x = (const float*)d_in[i];
        else if (sz == (long long)NTOT * KTOT)   w = d_in[i];
        else if (sz == (long long)NTOT * 128) {
            if (!sc) sc = (const float*)d_in[i];
            else     zr = (const float*)d_in[i];
        }
    }
    float* out = (float*)d_out;

    cudaFuncSetAttribute(gemm_kernel, cudaFuncAttributeMaxDynamicSharedMemorySize, SMEM_TOTAL);

    detect_kernel<<<1, 1024>>>((const int*)w);
    quant_kernel<<<MTOT, 256>>>(x);
    dequant_kernel<<<NTOT, 256>>>(w, sc, zr);
    gemm_kernel<<<NBLK * MBLK, 128, SMEM_TOTAL>>>(out);
}

// round 15
// speedup vs baseline: 1.0492x; 1.0492x over previous
#include <cuda_runtime.h>
#include <cuda_fp16.h>
#include <cstdint>

// ---------------- problem dims ----------------
#define MTOT 8192
#define NTOT 11008
#define KTOT 4096

// ---------------- GEMM tiling ----------------
#define BM 128
#define BN 128
#define BK 64
#define NITER (KTOT / BK)                  // 64
#define A_BYTES (BM * BK * 2)              // 16384
#define B_BYTES (BN * BK * 2)              // 16384
#define STG_BYTES (A_BYTES + B_BYTES)      // 32768
#define STAGES 3
#define SMEM_TOTAL (STAGES * STG_BYTES)    // 98304 per CTA -> 2 CTAs/SM
#define NBLK (NTOT / BN)                   // 86
#define MBLK (MTOT / BM)                   // 64
#define GROUP_M 8

// ---------------- device-global scratch (allowed) ----------------
__device__ __align__(1024) __half g_A[(size_t)MTOT * KTOT];   // exact int8 q as fp16
__device__ __align__(1024) __half g_B[(size_t)NTOT * KTOT];   // dequantized weights fp16
__device__ float g_as[MTOT];                                   // per-token activation scale
__device__ int g_w_is_i32;                                     // weight buffer layout flag

// ---------------- ptx helpers ----------------
static __device__ __forceinline__ uint32_t smem_u32(const void* p) {
    uint32_t a;
    asm("{ .reg .u64 t; cvta.to.shared.u64 t, %1; cvt.u32.u64 %0, t; }" : "=r"(a) : "l"(p));
    return a;
}

#define CP16(dst, src) \
    asm volatile("cp.async.cg.shared.global [%0], [%1], 16;" :: "r"(dst), "l"(src) : "memory")
#define CP_COMMIT() asm volatile("cp.async.commit_group;" ::: "memory")
#define CP_WAIT(n)  asm volatile("cp.async.wait_group %0;" :: "n"(n) : "memory")

static __device__ __forceinline__ void ldsm_x4(uint32_t* r, uint32_t addr) {
    asm volatile("ldmatrix.sync.aligned.m8n8.x4.shared.b16 {%0,%1,%2,%3}, [%4];"
                 : "=r"(r[0]), "=r"(r[1]), "=r"(r[2]), "=r"(r[3]) : "r"(addr));
}

static __device__ __forceinline__ void mma16816(float* d, const uint32_t* a,
                                                uint32_t b0, uint32_t b1) {
    asm volatile("mma.sync.aligned.m16n8k16.row.col.f32.f16.f16.f32 "
                 "{%0,%1,%2,%3}, {%4,%5,%6,%7}, {%8,%9}, {%0,%1,%2,%3};"
                 : "+f"(d[0]), "+f"(d[1]), "+f"(d[2]), "+f"(d[3])
                 : "r"(a[0]), "r"(a[1]), "r"(a[2]), "r"(a[3]), "r"(b0), "r"(b1));
}

// ==================== kernel 0: detect weight element width (parallel) =============
__global__ void detect_kernel(const int* __restrict__ w) {
    __shared__ int flag;
    int t = threadIdx.x;
    if (t == 0) flag = 1;
    __syncthreads();
    unsigned v = (unsigned)w[t];
    if (v >= 16u) flag = 0;        // benign race: all writers store 0
    __syncthreads();
    if (t == 0) g_w_is_i32 = flag;
}

// ==================== kernel 1: per-token int8 fake-quant -> fp16 ====================
__global__ void __launch_bounds__(256) quant_kernel(const float* __restrict__ x) {
    int row = blockIdx.x;
    int t = threadIdx.x;
    const float4* xr = (const float4*)(x + (size_t)row * KTOT);

    float4 v[4];
    float amax = 0.0f;
#pragma unroll
    for (int j = 0; j < 4; j++) {
        v[j] = xr[t + j * 256];
        amax = fmaxf(amax, fmaxf(fmaxf(fabsf(v[j].x), fabsf(v[j].y)),
                                 fmaxf(fabsf(v[j].z), fabsf(v[j].w))));
    }
#pragma unroll
    for (int o = 16; o; o >>= 1) amax = fmaxf(amax, __shfl_xor_sync(0xFFFFFFFFu, amax, o));
    __shared__ float red[8];
    if ((t & 31) == 0) red[t >> 5] = amax;
    __syncthreads();
    if (t < 32) {
        float m = (t < 8) ? red[t] : 0.0f;
#pragma unroll
        for (int o = 4; o; o >>= 1) m = fmaxf(m, __shfl_xor_sync(0xFFFFFFFFu, m, o));
        if (t == 0) red[0] = m;
    }
    __syncthreads();
    amax = red[0];
    float s = fmaxf(amax, 1e-12f) / 127.0f;
    if (t == 0) g_as[row] = s;

    __half* dst = g_A + (size_t)row * KTOT;
#pragma unroll
    for (int j = 0; j < 4; j++) {
        int f = t + j * 256;
        float q0 = fminf(fmaxf(rintf(v[j].x / s), -128.0f), 127.0f);
        float q1 = fminf(fmaxf(rintf(v[j].y / s), -128.0f), 127.0f);
        float q2 = fminf(fmaxf(rintf(v[j].z / s), -128.0f), 127.0f);
        float q3 = fminf(fmaxf(rintf(v[j].w / s), -128.0f), 127.0f);
        __half2 h01 = __floats2half2_rn(q0, q1);
        __half2 h23 = __floats2half2_rn(q2, q3);
        uint2 st;
        st.x = *(uint32_t*)&h01;
        st.y = *(uint32_t*)&h23;
        ((uint2*)dst)[f] = st;
    }
}

// ==================== kernel 2: int4 groupwise dequant -> fp16 (dual-format) ====
__global__ void __launch_bounds__(256) dequant_kernel(const void* __restrict__ wraw,
                                                      const float* __restrict__ sc,
                                                      const float* __restrict__ zr) {
    int row = blockIdx.x;
    int t = threadIdx.x;                       // 16 elements per thread
    float scale = sc[row * 128 + (t >> 1)];
    float zero  = zr[row * 128 + (t >> 1)];

    float f[16];
    if (g_w_is_i32) {
        const int4* p = (const int4*)((const int*)wraw + (size_t)row * KTOT + t * 16);
#pragma unroll
        for (int j = 0; j < 4; j++) {
            int4 v = p[j];
            f[j * 4 + 0] = (float)v.x;
            f[j * 4 + 1] = (float)v.y;
            f[j * 4 + 2] = (float)v.z;
            f[j * 4 + 3] = (float)v.w;
        }
    } else {
        int4 q = ((const int4*)((const int8_t*)wraw + (size_t)row * KTOT))[t];
        const int* qi = (const int*)&q;
#pragma unroll
        for (int i = 0; i < 4; i++) {
            int word = qi[i];
#pragma unroll
            for (int b = 0; b < 4; b++)
                f[i * 4 + b] = (float)((word >> (8 * b)) & 0xFF);
        }
    }

    __half h[16];
#pragma unroll
    for (int i = 0; i < 16; i++) h[i] = __float2half_rn((f[i] - zero) * scale);

    const uint32_t* hw = (const uint32_t*)h;
    uint4 s0, s1;
    s0.x = hw[0]; s0.y = hw[1]; s0.z = hw[2]; s0.w = hw[3];
    s1.x = hw[4]; s1.y = hw[5]; s1.z = hw[6]; s1.w = hw[7];
    uint4* dst = (uint4*)(g_B + (size_t)row * KTOT + t * 16);
    dst[0] = s0;
    dst[1] = s1;
}

// ==================== kernel 3: HMMA GEMM (64x64 warp tile, grouped raster) ========
// SMEM per stage: A [128 rows x 128B], B [128 rows x 128B].
// 16B chunk (r, c16) stored at byte r*128 + ((c16 ^ (r&7)) * 16).

static __device__ __forceinline__ void fetch_stage(uint32_t sb, int s, int ki,
                                                   int m0, int n0, int t) {
    uint32_t abase = sb + s * STG_BYTES;
    uint32_t bbase = abase + A_BYTES;
    size_t k0 = (size_t)ki * BK;
    int r0 = t >> 3, c = t & 7;
    uint32_t sw = (uint32_t)c;
    const char* gA = (const char*)(g_A + (size_t)m0 * KTOT + k0) + c * 16;
    const char* gB = (const char*)(g_B + (size_t)n0 * KTOT + k0) + c * 16;
#pragma unroll
    for (int j = 0; j < 8; j++) {
        int r = r0 + j * 16;
        uint32_t off = (uint32_t)(r * 128) + ((sw ^ (r & 7)) * 16);
        CP16(abase + off, gA + (size_t)r * (KTOT * 2));
    }
#pragma unroll
    for (int j = 0; j < 8; j++) {
        int r = r0 + j * 16;
        uint32_t off = (uint32_t)(r * 128) + ((sw ^ (r & 7)) * 16);
        CP16(bbase + off, gB + (size_t)r * (KTOT * 2));
    }
    CP_COMMIT();
}

__global__ void __launch_bounds__(128, 2) gemm_kernel(float* __restrict__ out) {
    extern __shared__ char smem[];
    uint32_t sb = smem_u32(smem);
    int t = threadIdx.x, wid = t >> 5, l = t & 31;

    // grouped rasterization: 8 m-blocks x 86 n-blocks per group -> wave working
    // set ~45MB (A 8MB + B 37MB), fits L2. (R14: DRAM 25% -> 9%.)
    int pid = blockIdx.x;
    const int group_size = GROUP_M * NBLK;          // 688
    int group_id = pid / group_size;
    int rem = pid - group_id * group_size;
    int m_blk = group_id * GROUP_M + (rem % GROUP_M);
    int n_blk = rem / GROUP_M;
    int m0 = m_blk * BM;
    int n0 = n_blk * BN;

    int wm = (wid & 1) * 64;          // 2 warps along M (64 each)
    int wn = (wid >> 1) * 64;         // 2 warps along N (64 each)

    float acc[4][8][4];
#pragma unroll
    for (int i = 0; i < 4; i++)
#pragma unroll
        for (int j = 0; j < 8; j++)
#pragma unroll
            for (int q = 0; q < 4; q++) acc[i][j][q] = 0.0f;

    // ldmatrix lane->row/chunk components
    int a_r = wm + (l & 15);                    // + mt*16
    int b_r = wn + (l & 7) + ((l >> 4) << 3);   // + np*16
    int a_chi = l >> 4;                         // A chunk: ks*2 + (l>>4)
    int b_chi = (l >> 3) & 1;                   // B chunk: ks*2 + ((l>>3)&1)

    // prologue: stages 0,1
    fetch_stage(sb, 0, 0, m0, n0, t);
    fetch_stage(sb, 1, 1, m0, n0, t);

    for (int i = 0; i < NITER; i++) {
        CP_WAIT(1);                 // fetch(i) complete (newest outstanding = fetch(i+1))
        __syncthreads();            // visibility + WAR guard for the fetch below

        uint32_t abase = sb + (i % 3) * STG_BYTES;
        uint32_t bbase = abase + A_BYTES;

#pragma unroll
        for (int ks = 0; ks < 4; ks++) {
            uint32_t af[4][4], bf[4][4];
#pragma unroll
            for (int mt = 0; mt < 4; mt++) {
                int r = a_r + mt * 16;
                uint32_t c16 = (uint32_t)(ks * 2 + a_chi);
                uint32_t addr = abase + (uint32_t)(r * 128) + ((c16 ^ (r & 7)) * 16);
                ldsm_x4(af[mt], addr);
            }
#pragma unroll
            for (int np = 0; np < 4; np++) {
                int r = b_r + np * 16;
                uint32_t c16 = (uint32_t)(ks * 2 + b_chi);
                uint32_t addr = bbase + (uint32_t)(r * 128) + ((c16 ^ (r & 7)) * 16);
                ldsm_x4(bf[np], addr);
            }
#pragma unroll
            for (int mt = 0; mt < 4; mt++)
#pragma unroll
                for (int np = 0; np < 4; np++) {
                    mma16816(acc[mt][np * 2],     af[mt], bf[np][0], bf[np][1]);
                    mma16816(acc[mt][np * 2 + 1], af[mt], bf[np][2], bf[np][3]);
                }
        }

        // fetch stage i+2 AFTER compute (R13 ordering — fetch-first regressed in R14):
        // overwrites stage (i-1)%3 whose readers all passed sync(i) -> hazard-free.
        fetch_stage(sb, (i + 2) % 3, (i + 2) & (NITER - 1), m0, n0, t);
    }

    // epilogue: per-row activation scale, direct float2 stores
    int gid = l >> 2;
    int cl = (l & 3) * 2;
#pragma unroll
    for (int mt = 0; mt < 4; mt++) {
        int row0 = m0 + wm + mt * 16 + gid;
        float s0 = g_as[row0];
        float s1 = g_as[row0 + 8];
        float* o0 = out + (size_t)row0 * NTOT + n0 + wn + cl;
        float* o1 = o0 + (size_t)8 * NTOT;
#pragma unroll
        for (int nt = 0; nt < 8; nt++) {
            float2 v0 = make_float2(acc[mt][nt][0] * s0, acc[mt][nt][1] * s0);
            float2 v1 = make_float2(acc[mt][nt][2] * s1, acc[mt][nt][3] * s1);
            *(float2*)(o0 + nt * 8) = v0;
            *(float2*)(o1 + nt * 8) = v1;
        }
    }
}

// ==================== launch ====================
extern "C" void kernel_launch(void* const* d_in, const int* in_sizes, int n_in,
                              void* d_out, int out_size) {
    const float* x  = nullptr;
    const void*  w  = nullptr;
    const float* sc = nullptr;
    const float* zr = nullptr;
    for (int i = 0; i < n_in; i++) {
        long long sz = (long long)in_sizes[i];
        if (sz == (long long)MTOT * KTOT)        x = (const float*)d_in[i];
        else if (sz == (long long)NTOT * KTOT)   w = d_in[i];
        else if (sz == (long long)NTOT * 128) {
            if (!sc) sc = (const float*)d_in[i];
            else     zr = (const float*)d_in[i];
        }
    }
    float* out = (float*)d_out;

    cudaFuncSetAttribute(gemm_kernel, cudaFuncAttributeMaxDynamicSharedMemorySize, SMEM_TOTAL);

    detect_kernel<<<1, 1024>>>((const int*)w);
    quant_kernel<<<MTOT, 256>>>(x);
    dequant_kernel<<<NTOT, 256>>>(w, sc, zr);
    gemm_kernel<<<NBLK * MBLK, 128, SMEM_TOTAL>>>(out);
}

// round 16
// speedup vs baseline: 1.1233x; 1.0706x over previous
#include <cuda_runtime.h>
#include <cuda_fp16.h>
#include <cstdint>

// ---------------- problem dims ----------------
#define MTOT 8192
#define NTOT 11008
#define KTOT 4096

// ---------------- GEMM tiling ----------------
#define BM 128
#define BN 128
#define BK 64
#define NITER (KTOT / BK)                  // 64
#define A_BYTES (BM * BK * 2)              // 16384
#define B_BYTES (BN * BK * 2)              // 16384
#define STG_BYTES (A_BYTES + B_BYTES)      // 32768
#define STAGES 3
#define SMEM_TOTAL (STAGES * STG_BYTES)    // 98304 per CTA -> 2 CTAs/SM
#define NBLK (NTOT / BN)                   // 86
#define MBLK (MTOT / BM)                   // 64
#define GROUP_M 8

// ---------------- device-global scratch (allowed) ----------------
__device__ __align__(1024) __half g_A[(size_t)MTOT * KTOT];   // exact int8 q as fp16
__device__ __align__(1024) __half g_B[(size_t)NTOT * KTOT];   // dequantized weights fp16
__device__ float g_as[MTOT];                                   // per-token activation scale
__device__ int g_w_is_i32;                                     // weight buffer layout flag

// ---------------- ptx helpers ----------------
static __device__ __forceinline__ uint32_t smem_u32(const void* p) {
    uint32_t a;
    asm("{ .reg .u64 t; cvta.to.shared.u64 t, %1; cvt.u32.u64 %0, t; }" : "=r"(a) : "l"(p));
    return a;
}

#define CP16(dst, src) \
    asm volatile("cp.async.cg.shared.global [%0], [%1], 16;" :: "r"(dst), "l"(src) : "memory")
#define CP_COMMIT() asm volatile("cp.async.commit_group;" ::: "memory")
#define CP_WAIT(n)  asm volatile("cp.async.wait_group %0;" :: "n"(n) : "memory")

static __device__ __forceinline__ void ldsm_x4(uint32_t* r, uint32_t addr) {
    asm volatile("ldmatrix.sync.aligned.m8n8.x4.shared.b16 {%0,%1,%2,%3}, [%4];"
                 : "=r"(r[0]), "=r"(r[1]), "=r"(r[2]), "=r"(r[3]) : "r"(addr));
}

static __device__ __forceinline__ void mma16816(float* d, const uint32_t* a,
                                                uint32_t b0, uint32_t b1) {
    asm volatile("mma.sync.aligned.m16n8k16.row.col.f32.f16.f16.f32 "
                 "{%0,%1,%2,%3}, {%4,%5,%6,%7}, {%8,%9}, {%0,%1,%2,%3};"
                 : "+f"(d[0]), "+f"(d[1]), "+f"(d[2]), "+f"(d[3])
                 : "r"(a[0]), "r"(a[1]), "r"(a[2]), "r"(a[3]), "r"(b0), "r"(b1));
}

// ==================== kernel 0: detect weight element width (parallel) =============
__global__ void detect_kernel(const int* __restrict__ w) {
    __shared__ int flag;
    int t = threadIdx.x;
    if (t == 0) flag = 1;
    __syncthreads();
    unsigned v = (unsigned)w[t];
    if (v >= 16u) flag = 0;        // benign race: all writers store 0
    __syncthreads();
    if (t == 0) g_w_is_i32 = flag;
}

// ==================== kernel 1: per-token int8 fake-quant -> fp16 ====================
__global__ void __launch_bounds__(256) quant_kernel(const float* __restrict__ x) {
    int row = blockIdx.x;
    int t = threadIdx.x;
    const float4* xr = (const float4*)(x + (size_t)row * KTOT);

    float4 v[4];
    float amax = 0.0f;
#pragma unroll
    for (int j = 0; j < 4; j++) {
        v[j] = xr[t + j * 256];
        amax = fmaxf(amax, fmaxf(fmaxf(fabsf(v[j].x), fabsf(v[j].y)),
                                 fmaxf(fabsf(v[j].z), fabsf(v[j].w))));
    }
#pragma unroll
    for (int o = 16; o; o >>= 1) amax = fmaxf(amax, __shfl_xor_sync(0xFFFFFFFFu, amax, o));
    __shared__ float red[8];
    if ((t & 31) == 0) red[t >> 5] = amax;
    __syncthreads();
    if (t < 32) {
        float m = (t < 8) ? red[t] : 0.0f;
#pragma unroll
        for (int o = 4; o; o >>= 1) m = fmaxf(m, __shfl_xor_sync(0xFFFFFFFFu, m, o));
        if (t == 0) red[0] = m;
    }
    __syncthreads();
    amax = red[0];
    float s = fmaxf(amax, 1e-12f) / 127.0f;
    if (t == 0) g_as[row] = s;

    __half* dst = g_A + (size_t)row * KTOT;
#pragma unroll
    for (int j = 0; j < 4; j++) {
        int f = t + j * 256;
        float q0 = fminf(fmaxf(rintf(v[j].x / s), -128.0f), 127.0f);
        float q1 = fminf(fmaxf(rintf(v[j].y / s), -128.0f), 127.0f);
        float q2 = fminf(fmaxf(rintf(v[j].z / s), -128.0f), 127.0f);
        float q3 = fminf(fmaxf(rintf(v[j].w / s), -128.0f), 127.0f);
        __half2 h01 = __floats2half2_rn(q0, q1);
        __half2 h23 = __floats2half2_rn(q2, q3);
        uint2 st;
        st.x = *(uint32_t*)&h01;
        st.y = *(uint32_t*)&h23;
        ((uint2*)dst)[f] = st;
    }
}

// ==================== kernel 2: int4 groupwise dequant -> fp16 (dual-format) ====
__global__ void __launch_bounds__(256) dequant_kernel(const void* __restrict__ wraw,
                                                      const float* __restrict__ sc,
                                                      const float* __restrict__ zr) {
    int row = blockIdx.x;
    int t = threadIdx.x;                       // 16 elements per thread
    float scale = sc[row * 128 + (t >> 1)];
    float zero  = zr[row * 128 + (t >> 1)];

    float f[16];
    if (g_w_is_i32) {
        const int4* p = (const int4*)((const int*)wraw + (size_t)row * KTOT + t * 16);
#pragma unroll
        for (int j = 0; j < 4; j++) {
            int4 v = p[j];
            f[j * 4 + 0] = (float)v.x;
            f[j * 4 + 1] = (float)v.y;
            f[j * 4 + 2] = (float)v.z;
            f[j * 4 + 3] = (float)v.w;
        }
    } else {
        int4 q = ((const int4*)((const int8_t*)wraw + (size_t)row * KTOT))[t];
        const int* qi = (const int*)&q;
#pragma unroll
        for (int i = 0; i < 4; i++) {
            int word = qi[i];
#pragma unroll
            for (int b = 0; b < 4; b++)
                f[i * 4 + b] = (float)((word >> (8 * b)) & 0xFF);
        }
    }

    __half h[16];
#pragma unroll
    for (int i = 0; i < 16; i++) h[i] = __float2half_rn((f[i] - zero) * scale);

    const uint32_t* hw = (const uint32_t*)h;
    uint4 s0, s1;
    s0.x = hw[0]; s0.y = hw[1]; s0.z = hw[2]; s0.w = hw[3];
    s1.x = hw[4]; s1.y = hw[5]; s1.z = hw[6]; s1.w = hw[7];
    uint4* dst = (uint4*)(g_B + (size_t)row * KTOT + t * 16);
    dst[0] = s0;
    dst[1] = s1;
}

// ==================== kernel 3: HMMA GEMM (frag double-buffer + sliced fetch) ======
// SMEM per stage: A [128 rows x 128B], B [128 rows x 128B].
// 16B chunk (r, c16) stored at byte r*128 + ((c16 ^ (r&7)) * 16).

static __device__ __forceinline__ void fetch_stage(uint32_t sb, int s, int ki,
                                                   int m0, int n0, int t) {
    uint32_t abase = sb + s * STG_BYTES;
    uint32_t bbase = abase + A_BYTES;
    size_t k0 = (size_t)ki * BK;
    int r0 = t >> 3, c = t & 7;
    uint32_t sw = (uint32_t)c;
    const char* gA = (const char*)(g_A + (size_t)m0 * KTOT + k0) + c * 16;
    const char* gB = (const char*)(g_B + (size_t)n0 * KTOT + k0) + c * 16;
#pragma unroll
    for (int j = 0; j < 8; j++) {
        int r = r0 + j * 16;
        uint32_t off = (uint32_t)(r * 128) + ((sw ^ (r & 7)) * 16);
        CP16(abase + off, gA + (size_t)r * (KTOT * 2));
    }
#pragma unroll
    for (int j = 0; j < 8; j++) {
        int r = r0 + j * 16;
        uint32_t off = (uint32_t)(r * 128) + ((sw ^ (r & 7)) * 16);
        CP16(bbase + off, gB + (size_t)r * (KTOT * 2));
    }
    CP_COMMIT();
}

// one quarter of a stage fetch: 2 A-rows + 2 B-rows per thread
static __device__ __forceinline__ void fetch_slice(uint32_t sb, int s, int ki,
                                                   int m0, int n0, int t, int sl) {
    uint32_t abase = sb + s * STG_BYTES;
    uint32_t bbase = abase + A_BYTES;
    size_t k0 = (size_t)ki * BK;
    int r0 = t >> 3, c = t & 7;
    uint32_t sw = (uint32_t)c;
    const char* gA = (const char*)(g_A + (size_t)m0 * KTOT + k0) + c * 16;
    const char* gB = (const char*)(g_B + (size_t)n0 * KTOT + k0) + c * 16;
#pragma unroll
    for (int j = 0; j < 2; j++) {
        int r = r0 + (sl * 2 + j) * 16;
        uint32_t off = (uint32_t)(r * 128) + ((sw ^ (r & 7)) * 16);
        CP16(abase + off, gA + (size_t)r * (KTOT * 2));
    }
#pragma unroll
    for (int j = 0; j < 2; j++) {
        int r = r0 + (sl * 2 + j) * 16;
        uint32_t off = (uint32_t)(r * 128) + ((sw ^ (r & 7)) * 16);
        CP16(bbase + off, gB + (size_t)r * (KTOT * 2));
    }
}

__global__ void __launch_bounds__(128, 2) gemm_kernel(float* __restrict__ out) {
    extern __shared__ char smem[];
    uint32_t sb = smem_u32(smem);
    int t = threadIdx.x, wid = t >> 5, l = t & 31;

    // grouped rasterization: wave working set ~45MB, fits L2 (DRAM ~9%).
    int pid = blockIdx.x;
    const int group_size = GROUP_M * NBLK;          // 688
    int group_id = pid / group_size;
    int rem = pid - group_id * group_size;
    int m_blk = group_id * GROUP_M + (rem % GROUP_M);
    int n_blk = rem / GROUP_M;
    int m0 = m_blk * BM;
    int n0 = n_blk * BN;

    int wm = (wid & 1) * 64;          // 2 warps along M (64 each)
    int wn = (wid >> 1) * 64;         // 2 warps along N (64 each)

    float acc[4][8][4];
#pragma unroll
    for (int i = 0; i < 4; i++)
#pragma unroll
        for (int j = 0; j < 8; j++)
#pragma unroll
            for (int q = 0; q < 4; q++) acc[i][j][q] = 0.0f;

    // ldmatrix lane->row/chunk components
    int a_r = wm + (l & 15);                    // + mt*16
    int b_r = wn + (l & 7) + ((l >> 4) << 3);   // + np*16
    int a_chi = l >> 4;                         // A chunk: ks*2 + (l>>4)
    int b_chi = (l >> 3) & 1;                   // B chunk: ks*2 + ((l>>3)&1)

    // prologue: stages 0,1
    fetch_stage(sb, 0, 0, m0, n0, t);
    fetch_stage(sb, 1, 1, m0, n0, t);

    uint32_t af[2][4][4], bf[2][4][4];   // double-buffered fragments across ks

    for (int i = 0; i < NITER; i++) {
        CP_WAIT(1);                 // fetch(i) complete (newest outstanding = fetch(i+1))
        __syncthreads();            // visibility + WAR guard for the sliced fetch below

        uint32_t abase = sb + (i % 3) * STG_BYTES;
        uint32_t bbase = abase + A_BYTES;
        int fs = (i + 2) % 3;                      // stage being refilled this iter
        int fk = (i + 2) & (NITER - 1);

        // load fragments for ks=0 into buffer 0
#pragma unroll
        for (int mt = 0; mt < 4; mt++) {
            int r = a_r + mt * 16;
            uint32_t c16 = (uint32_t)a_chi;
            ldsm_x4(af[0][mt], abase + (uint32_t)(r * 128) + ((c16 ^ (r & 7)) * 16));
        }
#pragma unroll
        for (int np = 0; np < 4; np++) {
            int r = b_r + np * 16;
            uint32_t c16 = (uint32_t)b_chi;
            ldsm_x4(bf[0][np], bbase + (uint32_t)(r * 128) + ((c16 ^ (r & 7)) * 16));
        }

#pragma unroll
        for (int ks = 0; ks < 4; ks++) {
            int cur = ks & 1, nxt = cur ^ 1;
            // prefetch fragments for ks+1 (hidden under this ks's 32 mmas)
            if (ks < 3) {
#pragma unroll
                for (int mt = 0; mt < 4; mt++) {
                    int r = a_r + mt * 16;
                    uint32_t c16 = (uint32_t)((ks + 1) * 2 + a_chi);
                    ldsm_x4(af[nxt][mt], abase + (uint32_t)(r * 128) + ((c16 ^ (r & 7)) * 16));
                }
#pragma unroll
                for (int np = 0; np < 4; np++) {
                    int r = b_r + np * 16;
                    uint32_t c16 = (uint32_t)((ks + 1) * 2 + b_chi);
                    ldsm_x4(bf[nxt][np], bbase + (uint32_t)(r * 128) + ((c16 ^ (r & 7)) * 16));
                }
            }
            // one quarter of next-stage fetch, spread behind the mma stream
            fetch_slice(sb, fs, fk, m0, n0, t, ks);
#pragma unroll
            for (int mt = 0; mt < 4; mt++)
#pragma unroll
                for (int np = 0; np < 4; np++) {
                    mma16816(acc[mt][np * 2],     af[cur][mt], bf[cur][np][0], bf[cur][np][1]);
                    mma16816(acc[mt][np * 2 + 1], af[cur][mt], bf[cur][np][2], bf[cur][np][3]);
                }
        }
        CP_COMMIT();                // one group per iteration (same wait semantics)
    }

    // epilogue: per-row activation scale, direct float2 stores
    int gid = l >> 2;
    int cl = (l & 3) * 2;
#pragma unroll
    for (int mt = 0; mt < 4; mt++) {
        int row0 = m0 + wm + mt * 16 + gid;
        float s0 = g_as[row0];
        float s1 = g_as[row0 + 8];
        float* o0 = out + (size_t)row0 * NTOT + n0 + wn + cl;
        float* o1 = o0 + (size_t)8 * NTOT;
#pragma unroll
        for (int nt = 0; nt < 8; nt++) {
            float2 v0 = make_float2(acc[mt][nt][0] * s0, acc[mt][nt][1] * s0);
            float2 v1 = make_float2(acc[mt][nt][2] * s1, acc[mt][nt][3] * s1);
            *(float2*)(o0 + nt * 8) = v0;
            *(float2*)(o1 + nt * 8) = v1;
        }
    }
}

// ==================== launch ====================
extern "C" void kernel_launch(void* const* d_in, const int* in_sizes, int n_in,
                              void* d_out, int out_size) {
    const float* x  = nullptr;
    const void*  w  = nullptr;
    const float* sc = nullptr;
    const float* zr = nullptr;
    for (int i = 0; i < n_in; i++) {
        long long sz = (long long)in_sizes[i];
        if (sz == (long long)MTOT * KTOT)        x = (const float*)d_in[i];
        else if (sz == (long long)NTOT * KTOT)   w = d_in[i];
        else if (sz == (long long)NTOT * 128) {
            if (!sc) sc = (const float*)d_in[i];
            else     zr = (const float*)d_in[i];
        }
    }
    float* out = (float*)d_out;

    cudaFuncSetAttribute(gemm_kernel, cudaFuncAttributeMaxDynamicSharedMemorySize, SMEM_TOTAL);

    detect_kernel<<<1, 1024>>>((const int*)w);
    quant_kernel<<<MTOT, 256>>>(x);
    dequant_kernel<<<NTOT, 256>>>(w, sc, zr);
    gemm_kernel<<<NBLK * MBLK, 128, SMEM_TOTAL>>>(out);
}